// round 1
// baseline (speedup 1.0000x reference)
#include <cuda_runtime.h>
#include <math.h>

#define Dd   1024
#define Ss   4096
#define Bb   4
#define MTOT (Bb*Ss)           // 16384 rows
#define NCAT 5120              // 5*D fused output cols
#define K2   2048              // 2*D
#define NC   64                // chunks per sequence
#define CL   64                // steps per chunk (NC*CL = S)
#define NPC  (Bb*NC*Dd)        // 262144 per-chunk channel slots
#define OUT_ELEMS (MTOT*Dd)    // 16777216

// ---------------- scratch (device globals: no runtime allocation allowed) ----------------
__device__ float g_Wcat[Dd*NCAT];        // packed [Wa|Wo|WB0|WB1|Wdt], row-major (K=1024, N=5120)
__device__ float g_bcat[NCAT];
__device__ float g_z[(size_t)MTOT*NCAT]; // fused GEMM output (alpha, omega, B0, B1, dt planes)
__device__ float g_states[(size_t)MTOT*K2]; // (16384 x 2048) scan states, interleaved (2d,2d+1)
__device__ float g_P[4*NPC];             // per-chunk composed affine: p, r, q1, q2 planes
__device__ float g_H[2*NPC];             // per-chunk starting states h1, h2 planes

__device__ __forceinline__ float softplus_f(float v) {
    return v > 20.0f ? v : log1pf(expf(v));
}

// Per-timestep coefficients. Transition matrix is [[a, b], [-b, a]].
__device__ __forceinline__ void step_coef(float alpha, float omega, float B0, float B1,
                                          float dt, float xv,
                                          float& a, float& bb, float& u0, float& u1) {
    float tau = 0.5f * dt;
    float opa = fmaf(tau, alpha, 1.0f);
    float tw  = tau * omega;
    float den = fmaf(opa, opa, fmaf(tw, tw, 1e-6f));
    float inv = 1.0f / den;
    float m11 = opa * inv;
    float m12 = tw  * inv;
    float oma = fmaf(-tau, alpha, 1.0f);
    a  = m11 * oma - m12 * tw;
    bb = m11 * tw  + m12 * oma;
    float Bx0 = B0 * xv;
    float Bx1 = B1 * xv;
    u0 = dt * fmaf(m11, Bx0,  m12 * Bx1);
    u1 = dt * fmaf(m11, Bx1, -m12 * Bx0);
}

// ---------------- pack weights: Wcat[k][n], de-interleaving WB ----------------
__global__ void pack_w(const float* __restrict__ Wa, const float* __restrict__ Wo,
                       const float* __restrict__ WB, const float* __restrict__ Wdt,
                       const float* __restrict__ ba, const float* __restrict__ bo,
                       const float* __restrict__ bB, const float* __restrict__ bdt) {
    int i = blockIdx.x * blockDim.x + threadIdx.x;
    if (i >= Dd * NCAT) return;
    int k = i / NCAT;
    int n = i - k * NCAT;
    int chunk = n >> 10;
    int j = n & 1023;
    float v;
    switch (chunk) {
        case 0:  v = Wa [k*Dd + j];        break;
        case 1:  v = Wo [k*Dd + j];        break;
        case 2:  v = WB [k*K2 + 2*j];      break;
        case 3:  v = WB [k*K2 + 2*j + 1];  break;
        default: v = Wdt[k*Dd + j];        break;
    }
    g_Wcat[i] = v;
    if (k == 0) {
        float bv;
        switch (chunk) {
            case 0:  bv = ba [j];       break;
            case 1:  bv = bo [j];       break;
            case 2:  bv = bB [2*j];     break;
            case 3:  bv = bB [2*j + 1]; break;
            default: bv = bdt[j];       break;
        }
        g_bcat[n] = bv;
    }
}

// ---------------- SIMT fp32 GEMM: 128x128 tile, BK=8, 8x8 microtile, 256 threads ----------------
// MODE 0: A=x (arg), B=g_Wcat, bias=g_bcat, C=g_z, softplus on chunks 0 and 4.
// MODE 1: A=g_states, B=WC (arg), bias=bC (arg), C=out (arg), plain bias.
template<int MODE>
__global__ void __launch_bounds__(256)
gemm_tile(const float* __restrict__ Aarg, const float* __restrict__ Barg,
          const float* __restrict__ biasArg, float* __restrict__ Carg,
          int N, int K) {
    const float* A    = (MODE == 0) ? Aarg     : g_states;
    const float* B    = (MODE == 0) ? g_Wcat   : Barg;
    const float* bias = (MODE == 0) ? g_bcat   : biasArg;
    float*       C    = (MODE == 0) ? g_z      : Carg;

    __shared__ float As[8][128];
    __shared__ float Bs[8][128];

    const int tid = threadIdx.x;
    const int tx = tid & 15;        // 0..15 -> N microtile
    const int ty = tid >> 4;        // 0..15 -> M microtile
    const int arow = tid >> 1;      // 0..127
    const int acol = (tid & 1) * 4; // 0 or 4
    const int brow = tid >> 5;      // 0..7
    const int bcol = (tid & 31) * 4;

    const float* Ap = A + (size_t)(blockIdx.y * 128 + arow) * K + acol;
    const float* Bp = B + (size_t)brow * N + blockIdx.x * 128 + bcol;

    float acc[8][8];
    #pragma unroll
    for (int i = 0; i < 8; i++)
        #pragma unroll
        for (int j = 0; j < 8; j++)
            acc[i][j] = 0.0f;

    for (int kt = 0; kt < K; kt += 8) {
        float4 av = *(const float4*)(Ap + kt);
        As[acol + 0][arow] = av.x;
        As[acol + 1][arow] = av.y;
        As[acol + 2][arow] = av.z;
        As[acol + 3][arow] = av.w;
        float4 bv = *(const float4*)(Bp + (size_t)kt * N);
        *(float4*)&Bs[brow][bcol] = bv;
        __syncthreads();
        #pragma unroll
        for (int k = 0; k < 8; k++) {
            float ar[8], br[8];
            *(float4*)(ar)     = *(const float4*)&As[k][ty * 8];
            *(float4*)(ar + 4) = *(const float4*)&As[k][ty * 8 + 4];
            *(float4*)(br)     = *(const float4*)&Bs[k][tx * 8];
            *(float4*)(br + 4) = *(const float4*)&Bs[k][tx * 8 + 4];
            #pragma unroll
            for (int i = 0; i < 8; i++)
                #pragma unroll
                for (int j = 0; j < 8; j++)
                    acc[i][j] = fmaf(ar[i], br[j], acc[i][j]);
        }
        __syncthreads();
    }

    int row0 = blockIdx.y * 128 + ty * 8;
    int col0 = blockIdx.x * 128 + tx * 8;
    #pragma unroll
    for (int i = 0; i < 8; i++) {
        #pragma unroll
        for (int j = 0; j < 8; j++) {
            int col = col0 + j;
            float v = acc[i][j] + bias[col];
            if (MODE == 0) {
                int chunk = col >> 10;
                if (chunk == 0 || chunk == 4) v = softplus_f(v);
            }
            C[(size_t)(row0 + i) * N + col] = v;
        }
    }
}

// ---------------- scan phase A: per-chunk affine composition ----------------
__global__ void __launch_bounds__(256) scan_phaseA(const float* __restrict__ x) {
    int gid = blockIdx.x * 256 + threadIdx.x;   // 0..NPC-1; gid == (b*NC+c)*D + d
    int d  = gid & (Dd - 1);
    int bc = gid >> 10;
    int b  = bc >> 6;
    int c  = bc & (NC - 1);
    int r0 = b * Ss + c * CL;

    float p = 1.0f, rr = 0.0f, q1 = 0.0f, q2 = 0.0f;
    for (int t = 0; t < CL; t++) {
        int r = r0 + t;
        size_t base = (size_t)r * NCAT;
        float alpha = g_z[base + d];
        float omega = g_z[base + 1024 + d];
        float B0    = g_z[base + 2048 + d];
        float B1    = g_z[base + 3072 + d];
        float dt    = g_z[base + 4096 + d];
        float xv    = x[(size_t)r * Dd + d];
        float a, bb, u0, u1;
        step_coef(alpha, omega, B0, B1, dt, xv, a, bb, u0, u1);
        // P' = A*P (both are [[p,r],[-r,p]] form), q' = A*q + u
        float np  = a * p  - bb * rr;
        float nr  = a * rr + bb * p;
        float nq1 =  a * q1 + bb * q2 + u0;
        float nq2 = -bb * q1 + a * q2 + u1;
        p = np; rr = nr; q1 = nq1; q2 = nq2;
    }
    g_P[0 * NPC + gid] = p;
    g_P[1 * NPC + gid] = rr;
    g_P[2 * NPC + gid] = q1;
    g_P[3 * NPC + gid] = q2;
}

// ---------------- scan phase B: across-chunk scan + final_state ----------------
__global__ void scan_phaseB(const float* __restrict__ state, float* __restrict__ out_final) {
    int gid = blockIdx.x * 256 + threadIdx.x;  // 0..4095 = b*D + d
    int d = gid & (Dd - 1);
    int b = gid >> 10;
    float h1 = state[(size_t)gid * 2 + 0];
    float h2 = state[(size_t)gid * 2 + 1];
    for (int c = 0; c < NC; c++) {
        int pc = (b * NC + c) * Dd + d;
        g_H[pc]       = h1;
        g_H[NPC + pc] = h2;
        float p  = g_P[pc];
        float rr = g_P[NPC + pc];
        float q1 = g_P[2 * NPC + pc];
        float q2 = g_P[3 * NPC + pc];
        float nh1 =  p * h1 + rr * h2 + q1;
        float nh2 = -rr * h1 + p * h2 + q2;
        h1 = nh1; h2 = nh2;
    }
    out_final[(size_t)gid * 2 + 0] = h1;
    out_final[(size_t)gid * 2 + 1] = h2;
}

// ---------------- scan phase C: replay chunk with correct start, write states ----------------
__global__ void __launch_bounds__(256) scan_phaseC(const float* __restrict__ x) {
    int gid = blockIdx.x * 256 + threadIdx.x;
    int d  = gid & (Dd - 1);
    int bc = gid >> 10;
    int b  = bc >> 6;
    int c  = bc & (NC - 1);
    int r0 = b * Ss + c * CL;

    float h1 = g_H[gid];
    float h2 = g_H[NPC + gid];
    float2* st2 = (float2*)g_states;
    for (int t = 0; t < CL; t++) {
        int r = r0 + t;
        size_t base = (size_t)r * NCAT;
        float alpha = g_z[base + d];
        float omega = g_z[base + 1024 + d];
        float B0    = g_z[base + 2048 + d];
        float B1    = g_z[base + 3072 + d];
        float dt    = g_z[base + 4096 + d];
        float xv    = x[(size_t)r * Dd + d];
        float a, bb, u0, u1;
        step_coef(alpha, omega, B0, B1, dt, xv, a, bb, u0, u1);
        float nh1 =  a * h1 + bb * h2 + u0;
        float nh2 = -bb * h1 + a * h2 + u1;
        h1 = nh1; h2 = nh2;
        st2[(size_t)r * Dd + d] = make_float2(h1, h2);  // cols (2d, 2d+1)
    }
}

// ---------------- launch ----------------
extern "C" void kernel_launch(void* const* d_in, const int* in_sizes, int n_in,
                              void* d_out, int out_size) {
    const float* x     = (const float*)d_in[0];
    const float* state = (const float*)d_in[1];
    const float* Wa    = (const float*)d_in[2];
    const float* ba    = (const float*)d_in[3];
    const float* Wo    = (const float*)d_in[4];
    const float* bo    = (const float*)d_in[5];
    const float* WB    = (const float*)d_in[6];
    const float* bB    = (const float*)d_in[7];
    const float* Wdt   = (const float*)d_in[8];
    const float *WC, *bC, *bdt;
    // setup_inputs dict order puts bdt last; disambiguate by size just in case.
    if (in_sizes[9] == K2 * Dd) {        // d_in[9] is WC (2M elements)
        WC  = (const float*)d_in[9];
        bC  = (const float*)d_in[10];
        bdt = (const float*)d_in[11];
    } else {                              // signature order: bdt, WC, bC
        bdt = (const float*)d_in[9];
        WC  = (const float*)d_in[10];
        bC  = (const float*)d_in[11];
    }
    float* out = (float*)d_out;

    // 1. pack fused weight/bias
    pack_w<<<(Dd * NCAT + 255) / 256, 256>>>(Wa, Wo, WB, Wdt, ba, bo, bB, bdt);

    // 2. fused input GEMM: z = act(x @ Wcat + bcat)   (16384 x 5120, K=1024)
    gemm_tile<0><<<dim3(NCAT / 128, MTOT / 128), 256>>>(x, nullptr, nullptr, nullptr, NCAT, Dd);

    // 3. chunked parallel scan
    scan_phaseA<<<NPC / 256, 256>>>(x);
    scan_phaseB<<<(Bb * Dd) / 256, 256>>>(state, out + OUT_ELEMS);
    scan_phaseC<<<NPC / 256, 256>>>(x);

    // 4. output GEMM: out = states @ WC + bC   (16384 x 1024, K=2048)
    gemm_tile<1><<<dim3(Dd / 128, MTOT / 128), 256>>>(nullptr, WC, bC, out, Dd, K2);
}

// round 5
// speedup vs baseline: 2.5868x; 2.5868x over previous
#include <cuda_runtime.h>
#include <cuda_bf16.h>
#include <stdint.h>
#include <math.h>

#define Dd   1024
#define Ss   4096
#define Bb   4
#define MTOT (Bb*Ss)           // 16384
#define NCAT 5120
#define K2   2048
#define NC   64
#define CL   64
#define NPC  (Bb*NC*Dd)
#define OUT_ELEMS ((size_t)MTOT*Dd)

// ---------------- device scratch ----------------
__device__ float4 g_coef[(size_t)MTOT*Dd];    // per-(t,d) scan coefficients (a,b,u0,u1)
__device__ float g_bcat[NCAT];                // bias, n = d*5+plane order
__device__ float g_P[4*NPC];
__device__ float g_H[2*NPC];
__device__ __nv_bfloat16 g_xhi[(size_t)MTOT*Dd];
__device__ __nv_bfloat16 g_xlo[(size_t)MTOT*Dd];
__device__ __nv_bfloat16 g_Wbhi[(size_t)NCAT*Dd];   // B GEMM1: [n][k], n = d*5+plane
__device__ __nv_bfloat16 g_Wblo[(size_t)NCAT*Dd];
__device__ __nv_bfloat16 g_wcthi[(size_t)Dd*K2];    // B GEMM2: [n][k]
__device__ __nv_bfloat16 g_wctlo[(size_t)Dd*K2];
__device__ __nv_bfloat16 g_shi[(size_t)MTOT*K2];    // A GEMM2 (states)
__device__ __nv_bfloat16 g_slo[(size_t)MTOT*K2];

// ---------------- helpers ----------------
__device__ __forceinline__ uint32_t smem_u32(const void* p) {
    uint32_t a;
    asm("{ .reg .u64 t; cvta.to.shared.u64 t, %1; cvt.u32.u64 %0, t; }" : "=r"(a) : "l"(p));
    return a;
}
#define SW128(o) ((o) ^ (((o) >> 3) & 0x70))

__device__ __forceinline__ void cpa16(uint32_t s, const void* g) {
    asm volatile("cp.async.cg.shared.global [%0], [%1], 16;" :: "r"(s), "l"(g));
}
#define CP_COMMIT() asm volatile("cp.async.commit_group;" ::: "memory")
#define CP_WAIT(n)  asm volatile("cp.async.wait_group %0;" :: "n"(n) : "memory")

#define LDSM4(r, addr) \
    asm volatile("ldmatrix.sync.aligned.m8n8.x4.shared.b16 {%0,%1,%2,%3}, [%4];" \
        : "=r"((r)[0]), "=r"((r)[1]), "=r"((r)[2]), "=r"((r)[3]) : "r"(addr))

#define MMA16816(d, a, b0, b1) \
    asm volatile("mma.sync.aligned.m16n8k16.row.col.f32.bf16.bf16.f32 " \
        "{%0,%1,%2,%3}, {%4,%5,%6,%7}, {%8,%9}, {%0,%1,%2,%3};" \
        : "+f"((d)[0]), "+f"((d)[1]), "+f"((d)[2]), "+f"((d)[3]) \
        : "r"((a)[0]), "r"((a)[1]), "r"((a)[2]), "r"((a)[3]), "r"(b0), "r"(b1))

__device__ __forceinline__ float softplus_f(float v) {
    return v > 20.0f ? v : log1pf(expf(v));
}
__device__ __forceinline__ void split_bf16(float v, __nv_bfloat16& hi, __nv_bfloat16& lo) {
    hi = __float2bfloat16_rn(v);
    lo = __float2bfloat16_rn(v - __bfloat162float(hi));
}
__device__ __forceinline__ void step_coef(float alpha, float omega, float B0, float B1,
                                          float dt, float xv,
                                          float& a, float& bb, float& u0, float& u1) {
    float tau = 0.5f * dt;
    float opa = fmaf(tau, alpha, 1.0f);
    float tw  = tau * omega;
    float den = fmaf(opa, opa, fmaf(tw, tw, 1e-6f));
    float inv = 1.0f / den;
    float m11 = opa * inv;
    float m12 = tw  * inv;
    float oma = fmaf(-tau, alpha, 1.0f);
    a  = m11 * oma - m12 * tw;
    bb = m11 * tw  + m12 * oma;
    float Bx0 = B0 * xv;
    float Bx1 = B1 * xv;
    u0 = dt * fmaf(m11, Bx0,  m12 * Bx1);
    u1 = dt * fmaf(m11, Bx1, -m12 * Bx0);
}

// ---------------- conversion / packing ----------------
__global__ void conv_x(const float4* __restrict__ x4) {
    size_t i = (size_t)blockIdx.x * 256 + threadIdx.x;
    float4 v = x4[i];
    __nv_bfloat16 h0,l0,h1,l1,h2,l2,h3,l3;
    split_bf16(v.x, h0, l0); split_bf16(v.y, h1, l1);
    split_bf16(v.z, h2, l2); split_bf16(v.w, h3, l3);
    __nv_bfloat162* hp = (__nv_bfloat162*)g_xhi;
    __nv_bfloat162* lp = (__nv_bfloat162*)g_xlo;
    hp[2*i]   = __nv_bfloat162(h0, h1);
    hp[2*i+1] = __nv_bfloat162(h2, h3);
    lp[2*i]   = __nv_bfloat162(l0, l1);
    lp[2*i+1] = __nv_bfloat162(l2, l3);
}

// pack fused weights to [n][k], n = d*5 + plane (channel-interleaved)
__global__ void pack_wcat(const float* __restrict__ Wa, const float* __restrict__ Wo,
                          const float* __restrict__ WB, const float* __restrict__ Wdt) {
    __shared__ float t[32][33];
    int k0 = blockIdx.x * 32;
    int n0 = blockIdx.y * 32;          // plane-major source index
    int plane = n0 >> 10;
    int j0 = n0 & 1023;
    int tx = threadIdx.x, ty = threadIdx.y;
    #pragma unroll
    for (int r = 0; r < 4; r++) {
        int k = k0 + ty + r * 8;
        int j = j0 + tx;
        float v;
        switch (plane) {
            case 0:  v = Wa [k*Dd + j];      break;
            case 1:  v = Wo [k*Dd + j];      break;
            case 2:  v = WB [k*K2 + 2*j];    break;
            case 3:  v = WB [k*K2 + 2*j+1];  break;
            default: v = Wdt[k*Dd + j];      break;
        }
        t[ty + r*8][tx] = v;
    }
    __syncthreads();
    #pragma unroll
    for (int r = 0; r < 4; r++) {
        int nl = ty + r * 8;                       // local d offset
        float v = t[tx][nl];
        __nv_bfloat16 hi, lo; split_bf16(v, hi, lo);
        int n = (j0 + nl) * 5 + plane;             // interleaved column
        size_t o = (size_t)n * Dd + k0 + tx;
        g_Wbhi[o] = hi; g_Wblo[o] = lo;
    }
}

__global__ void pack_wct(const float* __restrict__ WC) {
    __shared__ float t[32][33];
    int k0 = blockIdx.x * 32;
    int n0 = blockIdx.y * 32;
    int tx = threadIdx.x, ty = threadIdx.y;
    #pragma unroll
    for (int r = 0; r < 4; r++) {
        int k = k0 + ty + r * 8;
        t[ty + r*8][tx] = WC[(size_t)k * Dd + n0 + tx];
    }
    __syncthreads();
    #pragma unroll
    for (int r = 0; r < 4; r++) {
        int nl = ty + r * 8;
        float v = t[tx][nl];
        __nv_bfloat16 hi, lo; split_bf16(v, hi, lo);
        size_t o = (size_t)(n0 + nl) * K2 + k0 + tx;
        g_wcthi[o] = hi; g_wctlo[o] = lo;
    }
}

__global__ void pack_bias(const float* __restrict__ ba, const float* __restrict__ bo,
                          const float* __restrict__ bB, const float* __restrict__ bdt) {
    int n = blockIdx.x * 256 + threadIdx.x;   // interleaved index
    if (n >= NCAT) return;
    int d = n / 5, plane = n % 5;
    float v;
    switch (plane) {
        case 0:  v = ba [d];     break;
        case 1:  v = bo [d];     break;
        case 2:  v = bB [2*d];   break;
        case 3:  v = bB [2*d+1]; break;
        default: v = bdt[d];     break;
    }
    g_bcat[n] = v;
}

// ---------------- GEMM1 + fused coef epilogue ----------------
// CTA tile 128(M) x 160(N = 32 channels x 5 planes), 8 warps (4M x 2N), warp 32x80.
// KC=64, 2-stage cp.async. Epilogue: stage z-tile in smem, compute (a,b,u0,u1),
// write float4 g_coef.
#define KC 64
#define A_TB 16384                   // 128 rows x 128B
#define B_TB 20480                   // 160 rows x 128B
#define STG1 (2*A_TB + 2*B_TB)       // 73728
#define SMEM1 (2*STG1)               // 147456
#define ZST 165                      // z-tile smem stride (floats, odd -> conflict-free)

__global__ void __launch_bounds__(256, 1)
gemm1_coef(const float* __restrict__ x) {
    constexpr int KU4 = Dd / 8;      // 128
    constexpr int NCH = Dd / KC;     // 16
    const uint4* Ah4 = (const uint4*)g_xhi;
    const uint4* Al4 = (const uint4*)g_xlo;
    const uint4* Bh4 = (const uint4*)g_Wbhi;
    const uint4* Bl4 = (const uint4*)g_Wblo;

    extern __shared__ char smem[];
    const uint32_t sb = smem_u32(smem);
    const int tid = threadIdx.x, wid = tid >> 5, lid = tid & 31;
    const int wm = wid & 3, wn = wid >> 2;       // warp at (wm*32, wn*80)
    const int m0 = blockIdx.y * 128;
    const int n0 = blockIdx.x * 160;             // interleaved col base (mult of 5)
    const int d0 = blockIdx.x * 32;              // channel base

    float acc[2][10][4];
    #pragma unroll
    for (int i = 0; i < 2; i++)
        #pragma unroll
        for (int j = 0; j < 10; j++)
            #pragma unroll
            for (int q = 0; q < 4; q++) acc[i][j][q] = 0.0f;

    const int arow = lid & 15, ash = lid >> 4;
    const int brow = (lid & 7) | ((lid >> 4) << 3);
    const int bsh  = (lid >> 3) & 1;

    auto load_chunk = [&](int c, int bsel) {
        uint32_t stage = sb + bsel * STG1;
        #pragma unroll
        for (int i = 0; i < 4; i++) {            // A: 128 rows x 8 segs
            int idx = i * 256 + tid;
            int row = idx >> 3, j = idx & 7;
            uint32_t so = SW128(row * 128 + j * 16);
            size_t ga = (size_t)(m0 + row) * KU4 + c * 8 + j;
            cpa16(stage + so,        Ah4 + ga);
            cpa16(stage + A_TB + so, Al4 + ga);
        }
        #pragma unroll
        for (int i = 0; i < 5; i++) {            // B: 160 rows x 8 segs
            int idx = i * 256 + tid;
            int row = idx >> 3, j = idx & 7;
            uint32_t so = SW128(row * 128 + j * 16);
            size_t gb = (size_t)(n0 + row) * KU4 + c * 8 + j;
            cpa16(stage + 2*A_TB + so,        Bh4 + gb);
            cpa16(stage + 2*A_TB + B_TB + so, Bl4 + gb);
        }
    };

    load_chunk(0, 0);
    CP_COMMIT();

    for (int c = 0; c < NCH; c++) {
        if (c + 1 < NCH) {
            load_chunk(c + 1, (c + 1) & 1);
            CP_COMMIT();
            CP_WAIT(1);
        } else {
            CP_WAIT(0);
        }
        __syncthreads();

        uint32_t Ab  = sb + (c & 1) * STG1;
        uint32_t Alb = Ab + A_TB, Bbh = Ab + 2*A_TB, Bbl = Ab + 2*A_TB + B_TB;
        #pragma unroll
        for (int kk = 0; kk < KC; kk += 16) {
            uint32_t ah[2][4], al[2][4];
            #pragma unroll
            for (int mt = 0; mt < 2; mt++) {
                uint32_t off = SW128((uint32_t)((wm*32 + mt*16 + arow) * 128 + (kk + ash*8) * 2));
                LDSM4(ah[mt], Ab + off);
                LDSM4(al[mt], Alb + off);
            }
            #pragma unroll
            for (int nt = 0; nt < 5; nt++) {
                uint32_t bh[4], bl[4];
                uint32_t off = SW128((uint32_t)((wn*80 + nt*16 + brow) * 128 + (kk + bsh*8) * 2));
                LDSM4(bh, Bbh + off);
                LDSM4(bl, Bbl + off);
                #pragma unroll
                for (int mt = 0; mt < 2; mt++) {
                    MMA16816(acc[mt][2*nt],   ah[mt], bh[0], bh[1]);
                    MMA16816(acc[mt][2*nt],   ah[mt], bl[0], bl[1]);
                    MMA16816(acc[mt][2*nt],   al[mt], bh[0], bh[1]);
                    MMA16816(acc[mt][2*nt+1], ah[mt], bh[2], bh[3]);
                    MMA16816(acc[mt][2*nt+1], ah[mt], bl[2], bl[3]);
                    MMA16816(acc[mt][2*nt+1], al[mt], bh[2], bh[3]);
                }
            }
        }
        __syncthreads();
    }

    // ---- epilogue: stage z tile in smem with bias + activation ----
    float* zt = (float*)smem;                  // [128][ZST]
    const int qrow = lid >> 2, qc2 = (lid & 3) * 2;
    #pragma unroll
    for (int mt = 0; mt < 2; mt++) {
        #pragma unroll
        for (int j = 0; j < 10; j++) {
            int lcol = wn * 80 + j * 8 + qc2;
            float b0 = g_bcat[n0 + lcol], b1 = g_bcat[n0 + lcol + 1];
            int p0 = lcol % 5, p1 = (p0 + 1 == 5) ? 0 : p0 + 1;
            int r1 = wm * 32 + mt * 16 + qrow;
            float v0 = acc[mt][j][0] + b0, v1 = acc[mt][j][1] + b1;
            float v2 = acc[mt][j][2] + b0, v3 = acc[mt][j][3] + b1;
            if (p0 == 0 || p0 == 4) { v0 = softplus_f(v0); v2 = softplus_f(v2); }
            if (p1 == 0 || p1 == 4) { v1 = softplus_f(v1); v3 = softplus_f(v3); }
            zt[r1 * ZST + lcol]         = v0;
            zt[r1 * ZST + lcol + 1]     = v1;
            zt[(r1+8) * ZST + lcol]     = v2;
            zt[(r1+8) * ZST + lcol + 1] = v3;
        }
    }
    __syncthreads();

    // ---- coef pass: per (m, d) compute (a,b,u0,u1), write float4 ----
    const int dloc = tid & 31;
    const int mb   = tid >> 5;
    #pragma unroll 4
    for (int it = 0; it < 16; it++) {
        int m = mb + it * 8;
        const float* zr = zt + m * ZST + dloc * 5;
        float alpha = zr[0], omega = zr[1], B0v = zr[2], B1v = zr[3], dtv = zr[4];
        float xv = x[(size_t)(m0 + m) * Dd + d0 + dloc];
        float a, bb, u0, u1;
        step_coef(alpha, omega, B0v, B1v, dtv, xv, a, bb, u0, u1);
        g_coef[(size_t)(m0 + m) * Dd + d0 + dloc] = make_float4(a, bb, u0, u1);
    }
}

// ---------------- GEMM2: states @ WC + bC ----------------
#define TILE_B 16384
#define STG_B  (4*TILE_B)
#define SMEM2  (2*STG_B)

__global__ void __launch_bounds__(256, 1)
gemm2(const float* __restrict__ bias, float* __restrict__ C) {
    constexpr int Kt = K2, Nt = Dd;
    constexpr int NCH = Kt / KC;
    constexpr int KU4 = Kt / 8;
    const uint4* Ah4 = (const uint4*)g_shi;
    const uint4* Al4 = (const uint4*)g_slo;
    const uint4* Bh4 = (const uint4*)g_wcthi;
    const uint4* Bl4 = (const uint4*)g_wctlo;

    extern __shared__ char smem[];
    const uint32_t sb = smem_u32(smem);
    const int tid = threadIdx.x, wid = tid >> 5, lid = tid & 31;
    const int wm = wid & 1, wn = wid >> 1;
    const int m0 = blockIdx.y * 128;
    const int n0 = blockIdx.x * 128;

    float acc[4][4][4];
    #pragma unroll
    for (int i = 0; i < 4; i++)
        #pragma unroll
        for (int j = 0; j < 4; j++)
            #pragma unroll
            for (int q = 0; q < 4; q++) acc[i][j][q] = 0.0f;

    const int arow = lid & 15, ash = lid >> 4;
    const int brow = (lid & 7) | ((lid >> 4) << 3);
    const int bsh  = (lid >> 3) & 1;

    auto load_chunk = [&](int c, int bsel) {
        uint32_t stage = sb + bsel * STG_B;
        #pragma unroll
        for (int i = 0; i < 4; i++) {
            int idx = i * 256 + tid;
            int row = idx >> 3, j = idx & 7;
            uint32_t so = SW128(row * 128 + j * 16);
            size_t ga = (size_t)(m0 + row) * KU4 + c * 8 + j;
            size_t gb = (size_t)(n0 + row) * KU4 + c * 8 + j;
            cpa16(stage + 0*TILE_B + so, Ah4 + ga);
            cpa16(stage + 1*TILE_B + so, Al4 + ga);
            cpa16(stage + 2*TILE_B + so, Bh4 + gb);
            cpa16(stage + 3*TILE_B + so, Bl4 + gb);
        }
    };

    load_chunk(0, 0);
    CP_COMMIT();

    for (int c = 0; c < NCH; c++) {
        if (c + 1 < NCH) {
            load_chunk(c + 1, (c + 1) & 1);
            CP_COMMIT();
            CP_WAIT(1);
        } else {
            CP_WAIT(0);
        }
        __syncthreads();

        uint32_t Ab = sb + (c & 1) * STG_B;
        uint32_t Alb = Ab + TILE_B, Bbh = Ab + 2*TILE_B, Bbl = Ab + 3*TILE_B;
        #pragma unroll
        for (int kk = 0; kk < KC; kk += 16) {
            uint32_t ah[4][4], al[4][4], bh[2][4], bl[2][4];
            #pragma unroll
            for (int mt = 0; mt < 4; mt++) {
                uint32_t off = SW128((uint32_t)((wm*64 + mt*16 + arow) * 128 + (kk + ash*8) * 2));
                LDSM4(ah[mt], Ab + off);
                LDSM4(al[mt], Alb + off);
            }
            #pragma unroll
            for (int nt = 0; nt < 2; nt++) {
                uint32_t off = SW128((uint32_t)((wn*32 + nt*16 + brow) * 128 + (kk + bsh*8) * 2));
                LDSM4(bh[nt], Bbh + off);
                LDSM4(bl[nt], Bbl + off);
            }
            #pragma unroll
            for (int mt = 0; mt < 4; mt++) {
                #pragma unroll
                for (int n8 = 0; n8 < 4; n8++) {
                    int nt = n8 >> 1, h = (n8 & 1) * 2;
                    MMA16816(acc[mt][n8], ah[mt], bh[nt][h], bh[nt][h+1]);
                    MMA16816(acc[mt][n8], ah[mt], bl[nt][h], bl[nt][h+1]);
                    MMA16816(acc[mt][n8], al[mt], bh[nt][h], bh[nt][h+1]);
                }
            }
        }
        __syncthreads();
    }

    const int mrow = lid >> 2, nc2 = (lid & 3) * 2;
    #pragma unroll
    for (int mt = 0; mt < 4; mt++) {
        #pragma unroll
        for (int n8 = 0; n8 < 4; n8++) {
            int n = n0 + wn * 32 + n8 * 8 + nc2;
            float b0 = bias[n], b1 = bias[n + 1];
            int m = m0 + wm * 64 + mt * 16 + mrow;
            *(float2*)(C + (size_t)m * Nt + n)       = make_float2(acc[mt][n8][0] + b0, acc[mt][n8][1] + b1);
            *(float2*)(C + (size_t)(m + 8) * Nt + n) = make_float2(acc[mt][n8][2] + b0, acc[mt][n8][3] + b1);
        }
    }
}

// ---------------- scan ----------------
__global__ void __launch_bounds__(256) scan_phaseA() {
    int gid = blockIdx.x * 256 + threadIdx.x;
    int d  = gid & (Dd - 1);
    int bc = gid >> 10;
    int b  = bc >> 6;
    int c  = bc & (NC - 1);
    int r0 = b * Ss + c * CL;
    float p = 1.0f, rr = 0.0f, q1 = 0.0f, q2 = 0.0f;
    for (int t = 0; t < CL; t++) {
        float4 cf = g_coef[(size_t)(r0 + t) * Dd + d];
        float a = cf.x, bb = cf.y, u0 = cf.z, u1 = cf.w;
        float np  = a * p  - bb * rr;
        float nr  = a * rr + bb * p;
        float nq1 =  a * q1 + bb * q2 + u0;
        float nq2 = -bb * q1 + a * q2 + u1;
        p = np; rr = nr; q1 = nq1; q2 = nq2;
    }
    g_P[0 * NPC + gid] = p;
    g_P[1 * NPC + gid] = rr;
    g_P[2 * NPC + gid] = q1;
    g_P[3 * NPC + gid] = q2;
}

__global__ void scan_phaseB(const float* __restrict__ state, float* __restrict__ out_final) {
    int gid = blockIdx.x * 256 + threadIdx.x;
    int d = gid & (Dd - 1);
    int b = gid >> 10;
    float h1 = state[(size_t)gid * 2 + 0];
    float h2 = state[(size_t)gid * 2 + 1];
    for (int c = 0; c < NC; c++) {
        int pc = (b * NC + c) * Dd + d;
        g_H[pc]       = h1;
        g_H[NPC + pc] = h2;
        float p  = g_P[pc];
        float rr = g_P[NPC + pc];
        float q1 = g_P[2 * NPC + pc];
        float q2 = g_P[3 * NPC + pc];
        float nh1 =  p * h1 + rr * h2 + q1;
        float nh2 = -rr * h1 + p * h2 + q2;
        h1 = nh1; h2 = nh2;
    }
    out_final[(size_t)gid * 2 + 0] = h1;
    out_final[(size_t)gid * 2 + 1] = h2;
}

__global__ void __launch_bounds__(256) scan_phaseC() {
    int gid = blockIdx.x * 256 + threadIdx.x;
    int d  = gid & (Dd - 1);
    int bc = gid >> 10;
    int b  = bc >> 6;
    int c  = bc & (NC - 1);
    int r0 = b * Ss + c * CL;
    float h1 = g_H[gid];
    float h2 = g_H[NPC + gid];
    __nv_bfloat162* shi = (__nv_bfloat162*)g_shi;
    __nv_bfloat162* slo = (__nv_bfloat162*)g_slo;
    for (int t = 0; t < CL; t++) {
        int r = r0 + t;
        float4 cf = g_coef[(size_t)r * Dd + d];
        float a = cf.x, bb = cf.y, u0 = cf.z, u1 = cf.w;
        float nh1 =  a * h1 + bb * h2 + u0;
        float nh2 = -bb * h1 + a * h2 + u1;
        h1 = nh1; h2 = nh2;
        __nv_bfloat16 h1h, h1l, h2h, h2l;
        split_bf16(h1, h1h, h1l);
        split_bf16(h2, h2h, h2l);
        size_t o = (size_t)r * Dd + d;
        shi[o] = __nv_bfloat162(h1h, h2h);
        slo[o] = __nv_bfloat162(h1l, h2l);
    }
}

// ---------------- launch ----------------
extern "C" void kernel_launch(void* const* d_in, const int* in_sizes, int n_in,
                              void* d_out, int out_size) {
    const float* x     = (const float*)d_in[0];
    const float* state = (const float*)d_in[1];
    const float* Wa    = (const float*)d_in[2];
    const float* ba    = (const float*)d_in[3];
    const float* Wo    = (const float*)d_in[4];
    const float* bo    = (const float*)d_in[5];
    const float* WB    = (const float*)d_in[6];
    const float* bB    = (const float*)d_in[7];
    const float* Wdt   = (const float*)d_in[8];
    const float *WC, *bC, *bdt;
    if (in_sizes[9] == K2 * Dd) {
        WC  = (const float*)d_in[9];
        bC  = (const float*)d_in[10];
        bdt = (const float*)d_in[11];
    } else {
        bdt = (const float*)d_in[9];
        WC  = (const float*)d_in[10];
        bC  = (const float*)d_in[11];
    }
    float* out = (float*)d_out;

    cudaFuncSetAttribute(gemm1_coef, cudaFuncAttributeMaxDynamicSharedMemorySize, SMEM1);
    cudaFuncSetAttribute(gemm2,      cudaFuncAttributeMaxDynamicSharedMemorySize, SMEM2);

    conv_x<<<(MTOT * Dd / 4) / 256, 256>>>((const float4*)x);
    pack_wcat<<<dim3(Dd / 32, NCAT / 32), dim3(32, 8)>>>(Wa, Wo, WB, Wdt);
    pack_wct<<<dim3(K2 / 32, Dd / 32), dim3(32, 8)>>>(WC);
    pack_bias<<<(NCAT + 255) / 256, 256>>>(ba, bo, bB, bdt);

    gemm1_coef<<<dim3(NCAT / 160, MTOT / 128), 256, SMEM1>>>(x);

    scan_phaseA<<<NPC / 256, 256>>>();
    scan_phaseB<<<(Bb * Dd) / 256, 256>>>(state, out + OUT_ELEMS);
    scan_phaseC<<<NPC / 256, 256>>>();

    gemm2<<<dim3(Dd / 128, MTOT / 128), 256, SMEM2>>>(bC, out);
}